// round 15
// baseline (speedup 1.0000x reference)
#include <cuda_runtime.h>
#include <cuda_fp16.h>
#include <cstdint>

#define BB 64
#define TT 1024
#define II 128
#define HH 512

static constexpr int   NCTA2 = 64;
static constexpr int   THR2  = 256;   // 8 warps: 2 k-halves x 4 m-tiles
static constexpr float DT_C  = 0.1f;
static constexpr float EPS_C = 1e-8f;

// ---------------- device scratch ----------------
// g_st: per step t, per CTA jb, per batch b: 8 sens + 8 tcx halves (contiguous 2KB per (t,jb))
__device__ __align__(16)  __half g_st[(size_t)TT * 64 * 64 * 16];
// g_hbuf: ping-pong h, SWIZZLED image: row b (1024B), 16B chunk c stored at chunk (c ^ (b&7))
__device__ __align__(128) __half g_hbuf[2 * BB * HH];    // 2 x 64 KB
// per-warp arrival counters: parity p uses words [p*64 .. p*64+7] (one 32B sector)
__device__ __align__(256) unsigned g_cnt[2 * 64];
__device__ unsigned g_bar;   // unused, kept for reset symmetry

// ---------------- helpers ----------------
__device__ __forceinline__ unsigned smem_u32(const void* p) {
    return (unsigned)__cvta_generic_to_shared(p);
}
__device__ __forceinline__ void mma16816(float* c,
                                         unsigned a0, unsigned a1, unsigned a2, unsigned a3,
                                         unsigned b0, unsigned b1) {
    asm volatile(
        "mma.sync.aligned.m16n8k16.row.col.f32.f16.f16.f32 "
        "{%0,%1,%2,%3},{%4,%5,%6,%7},{%8,%9},{%0,%1,%2,%3};\n"
        : "+f"(c[0]), "+f"(c[1]), "+f"(c[2]), "+f"(c[3])
        : "r"(a0), "r"(a1), "r"(a2), "r"(a3), "r"(b0), "r"(b1));
}
__device__ __forceinline__ void ldsm4(unsigned& r0, unsigned& r1, unsigned& r2, unsigned& r3,
                                      unsigned addr) {
    asm volatile("ldmatrix.sync.aligned.m8n8.x4.shared.b16 {%0,%1,%2,%3},[%4];\n"
                 : "=r"(r0), "=r"(r1), "=r"(r2), "=r"(r3) : "r"(addr));
}
__device__ __forceinline__ uint4 pack8f(float4 f0, float4 f1) {
    __half2 h0 = __floats2half2_rn(f0.x, f0.y), h1 = __floats2half2_rn(f0.z, f0.w);
    __half2 h2 = __floats2half2_rn(f1.x, f1.y), h3 = __floats2half2_rn(f1.z, f1.w);
    uint4 pv;
    pv.x = *reinterpret_cast<unsigned*>(&h0); pv.y = *reinterpret_cast<unsigned*>(&h1);
    pv.z = *reinterpret_cast<unsigned*>(&h2); pv.w = *reinterpret_cast<unsigned*>(&h3);
    return pv;
}
__device__ __forceinline__ void bulk_g2s(uint32_t dst, const void* src, uint32_t bytes,
                                         uint32_t mbar) {
    asm volatile(
        "cp.async.bulk.shared::cluster.global.mbarrier::complete_tx::bytes [%0], [%1], %2, [%3];\n"
        :: "r"(dst), "l"(src), "r"(bytes), "r"(mbar) : "memory");
}
#define MBAR_INIT(a, n) \
    asm volatile("mbarrier.init.shared.b64 [%0], %1;" :: "r"(a), "r"((unsigned)(n)) : "memory")
#define MBAR_EXPECT_TX(a, n) \
    asm volatile("mbarrier.arrive.expect_tx.shared.b64 _, [%0], %1;" :: "r"(a), "r"((unsigned)(n)) : "memory")
__device__ __forceinline__ void mbar_wait(uint32_t a, uint32_t parity) {
    asm volatile(
        "{\n\t.reg .pred P1;\n\t"
        "WAIT_LOOP_%=:\n\t"
        "mbarrier.try_wait.parity.acquire.cta.shared::cta.b64 P1, [%0], %1, 0x989680;\n\t"
        "@P1 bra.uni WAIT_DONE_%=;\n\t"
        "bra.uni WAIT_LOOP_%=;\n\t"
        "WAIT_DONE_%=:\n\t}"
        :: "r"(a), "r"(parity) : "memory");
}
#define FENCE_PROXY_ASYNC_FULL() asm volatile("fence.proxy.async;" ::: "memory")

// ---------------- phase 1: input projections -> g_st ----------------
#define P1_PITCH 136
struct P1Smem {
    __half A[128 * P1_PITCH];
    __half W[128 * P1_PITCH];
    __half sens[128 * 32];
    __half tcx[128 * 32];
};

__global__ void phase1_kernel(const float* __restrict__ x,
                              const float* __restrict__ Wsw, const float* __restrict__ Wsm,
                              const float* __restrict__ Wss, const float* __restrict__ Wtcx,
                              const float* __restrict__ bsw, const float* __restrict__ bsm,
                              const float* __restrict__ bss, const float* __restrict__ btc) {
    extern __shared__ char smem_raw[];
    P1Smem& S = *reinterpret_cast<P1Smem*>(smem_raw);
    const int tid = threadIdx.x;
    const int m0 = blockIdx.x * 128;
    const int j0 = blockIdx.y * 32;

    // block (0,0): reset ALL barrier counter words + init h0 image to ones
    if (blockIdx.x == 0 && blockIdx.y == 0) {
        if (tid < 8) { g_cnt[tid] = 0; g_cnt[64 + tid] = 0; }
        if (tid == 8) g_bar = 0;
        uint4 ones = make_uint4(0x3C003C00u, 0x3C003C00u, 0x3C003C00u, 0x3C003C00u);
        for (int i = tid; i < BB * HH / 8; i += 256)
            *reinterpret_cast<uint4*>(&g_hbuf[i * 8]) = ones;
    }

    for (int i = tid; i < 128 * 16; i += 256) {
        int r = i >> 4, c = i & 15;
        const float4* src = reinterpret_cast<const float4*>(x + (size_t)(m0 + r) * II + c * 8);
        *reinterpret_cast<uint4*>(&S.A[r * P1_PITCH + c * 8]) = pack8f(src[0], src[1]);
    }
    const float* Wp[4] = { Wsw, Wsm, Wss, Wtcx };
    for (int i = tid; i < 128 * 16; i += 256) {
        int r = i >> 4, c = i & 15;
        int mat = r >> 5, jj = r & 31;
        const float4* src = reinterpret_cast<const float4*>(Wp[mat] + (size_t)(j0 + jj) * II + c * 8);
        *reinterpret_cast<uint4*>(&S.W[r * P1_PITCH + c * 8]) = pack8f(src[0], src[1]);
    }
    __syncthreads();

    const int lane = tid & 31, warp = tid >> 5;
    const int g = lane >> 2, t = lane & 3;
    float acc[16][4];
#pragma unroll
    for (int nt = 0; nt < 16; nt++)
#pragma unroll
        for (int q = 0; q < 4; q++) acc[nt][q] = 0.f;

    const int ar0 = (warp * 16 + g) * P1_PITCH;
    const int ar1 = (warp * 16 + g + 8) * P1_PITCH;
#pragma unroll
    for (int ks = 0; ks < 8; ks++) {
        const int k0 = ks * 16 + 2 * t;
        unsigned a0 = *reinterpret_cast<unsigned*>(&S.A[ar0 + k0]);
        unsigned a1 = *reinterpret_cast<unsigned*>(&S.A[ar1 + k0]);
        unsigned a2 = *reinterpret_cast<unsigned*>(&S.A[ar0 + k0 + 8]);
        unsigned a3 = *reinterpret_cast<unsigned*>(&S.A[ar1 + k0 + 8]);
#pragma unroll
        for (int nt = 0; nt < 16; nt++) {
            unsigned b0 = *reinterpret_cast<unsigned*>(&S.W[(nt * 8 + g) * P1_PITCH + k0]);
            unsigned b1 = *reinterpret_cast<unsigned*>(&S.W[(nt * 8 + g) * P1_PITCH + k0 + 8]);
            mma16816(acc[nt], a0, a1, a2, a3, b0, b1);
        }
    }

#pragma unroll
    for (int jb = 0; jb < 4; jb++) {
#pragma unroll
        for (int ri = 0; ri < 2; ri++) {
#pragma unroll
            for (int tt = 0; tt < 2; tt++) {
                int q = ri * 2 + tt;
                int jl = jb * 8 + 2 * t + tt;
                int jg = j0 + jl;
                float sw   = acc[0 * 4 + jb][q] + bsw[jg];
                float smu  = acc[1 * 4 + jb][q] + bsm[jg];
                float ssig = acc[2 * 4 + jb][q] + bss[jg];
                float tc   = acc[3 * 4 + jb][q] + btc[jg];
                float sig  = __fdividef(1.f, 1.f + __expf(-smu));
                float sens = sw * sig * __expf(fminf(ssig, 50.f));
                int ml = warp * 16 + g + ri * 8;
                S.sens[ml * 32 + jl] = __float2half(sens);
                S.tcx [ml * 32 + jl] = __float2half(tc);
            }
        }
    }
    __syncthreads();

    // write-out: g_st[t][jb][b][0:8]=sens, [8:16]=tcx
    {
        int r = tid & 127;
        int m = m0 + r;
        int b = m >> 10, tm = m & 1023;
        int jb0 = j0 >> 3;
#pragma unroll
        for (int jbl = 0; jbl < 4; jbl++) {
            size_t dst = (((size_t)tm * 64 + jb0 + jbl) * 64 + b) * 16;
            if (tid < 128) {
                *reinterpret_cast<uint4*>(g_st + dst) =
                    *reinterpret_cast<const uint4*>(&S.sens[r * 32 + jbl * 8]);
            } else {
                *reinterpret_cast<uint4*>(g_st + dst + 8) =
                    *reinterpret_cast<const uint4*>(&S.tcx[r * 32 + jbl * 8]);
            }
        }
    }
}

// ---------------- phase 2: recurrence ----------------
// 64 CTAs; CTA c owns hidden units [8c, 8c+8). 8 warps: warp = kh*4 + mw.
// B-fragments in registers all 1024 steps. h staged as 4 row-chunked 16KB bulks
// (warp kh*4+mw waits only on chunk mw). Symmetric split-K exchange; all warps
// run the epilogue (2 units each) and STG their outputs directly.
// DECENTRALIZED barrier: each warp (syncwarp + lane0) red.release's its own
// counter word g_cnt[p*64+warp] right after its epilogue; tid0 polls the 8-word
// sector for sum == 512*((s>>1)+1), then issues next-step TMAs. No CTA-wide
// sync in the tail; next-step mbar_wait gates all warps transitively.
#define WST_PITCH 520
struct P2Smem {
    __half  Hs[BB * HH];         // 64KB linear (row b: 1024B, chunks XOR-swizzled)
    __half  Wst[32 * WST_PITCH]; // one-time weight staging
    __half  st[2][64 * 16];      // sens/tcx double buffer (bulk dst)
    float   rbuf[2][4 * 8 * 32]; // split-K partials: [src kh][(mw*8+mt*2+tt)*32+lane]
    unsigned long long mb_h[4];  // per-row-chunk h barriers
    unsigned long long mb_st[2]; // sens/tcx prefetch barriers
};

__global__ void __launch_bounds__(THR2, 1)
phase2_kernel(float* __restrict__ out,
              const float* __restrict__ Wtch, const float* __restrict__ Wiw,
              const float* __restrict__ Wim,  const float* __restrict__ Wis,
              const float* __restrict__ biw, const float* __restrict__ bim,
              const float* __restrict__ bis) {
    extern __shared__ char smem_raw[];
    P2Smem& S = *reinterpret_cast<P2Smem*>(smem_raw);
    const int tid  = threadIdx.x;
    const int cta  = blockIdx.x;
    const int lane = tid & 31, warp = tid >> 5;
    const int mw = warp & 3, kh = warp >> 2;
    const int g = lane >> 2, t = lane & 3;

    const uint32_t HSb  = smem_u32(&S.Hs[0]);
    const uint32_t STb  = smem_u32(&S.st[0][0]);
    const uint32_t MBH  = smem_u32(&S.mb_h[0]);
    const uint32_t MBST = smem_u32(&S.mb_st[0]);

    // ---- one-time: stage weights (fp32 -> fp16) and preload B frags ----
    const float* Wp[4] = { Wtch, Wiw, Wim, Wis };
    for (int i = tid; i < 32 * 64; i += THR2) {
        int r = i >> 6, c8 = (i & 63) * 8;
        int mat = r >> 3, jj = r & 7;
        const float4* src = reinterpret_cast<const float4*>(
            Wp[mat] + (size_t)(cta * 8 + jj) * HH + c8);
        *reinterpret_cast<uint4*>(&S.Wst[r * WST_PITCH + c8]) = pack8f(src[0], src[1]);
    }
    if (tid == 0) {
#pragma unroll
        for (int c = 0; c < 4; c++) MBAR_INIT(MBH + c * 8, 1);
        MBAR_INIT(MBST + 0, 1);
        MBAR_INIT(MBST + 8, 1);
    }
    __syncthreads();
    FENCE_PROXY_ASYNC_FULL();   // one-time: mbarrier/SMEM init visible to async proxy
    __syncthreads();

    // preamble: issue h(step0) as 4 chunks + st(step0) + st(step1)
    if (tid == 0) {
#pragma unroll
        for (int c = 0; c < 4; c++) {
            MBAR_EXPECT_TX(MBH + c * 8, 16384);
            bulk_g2s(HSb + (unsigned)c * 16384u, (const char*)g_hbuf + c * 16384,
                     16384, MBH + c * 8);
        }
        MBAR_EXPECT_TX(MBST + 0, 2048);
        bulk_g2s(STb, (const char*)g_st + ((size_t)cta * 2048), 2048, MBST + 0);
        MBAR_EXPECT_TX(MBST + 8, 2048);
        bulk_g2s(STb + 2048u, (const char*)g_st + (((size_t)64 + cta) * 2048), 2048, MBST + 8);
    }

    unsigned bfr[16][4][2];
#pragma unroll
    for (int ks = 0; ks < 16; ks++) {
        const int k0 = kh * 256 + ks * 16 + 2 * t;
#pragma unroll
        for (int mt = 0; mt < 4; mt++) {
            bfr[ks][mt][0] = *reinterpret_cast<unsigned*>(&S.Wst[(mt * 8 + g) * WST_PITCH + k0]);
            bfr[ks][mt][1] = *reinterpret_cast<unsigned*>(&S.Wst[(mt * 8 + g) * WST_PITCH + k0 + 8]);
        }
    }

    float biwv[2], bimv[2], bisv[2];
    {
        int jg = cta * 8 + 2 * t;
        biwv[0] = biw[jg]; biwv[1] = biw[jg + 1];
        bimv[0] = bim[jg]; bimv[1] = bim[jg + 1];
        bisv[0] = bis[jg]; bisv[1] = bis[jg + 1];
    }
    // this thread's epilogue row/units: row bl = mw*16 + g + kh*8, units 2t/2t+1
    const int bl = mw * 16 + g + kh * 8;
    float h_master[2];
    h_master[0] = 1.0f; h_master[1] = 1.0f;

    // ldmatrix addressing (swizzled): row = mw*16 + (lane&15)
    const int arow   = mw * 16 + (lane & 15);
    const unsigned rowbase = HSb + (unsigned)arow * 1024u;
    const unsigned rowx    = (unsigned)(arow & 7);
    const unsigned chunk0  = (unsigned)(kh * 32 + (lane >> 4));
    const unsigned pub_chunk_off = ((unsigned)(cta ^ g)) * 16u + (unsigned)t * 4u;
    const int rb = (mw * 8 + 0) * 32 + lane;   // base rbuf slot (mt=0, tt=0)
    const uint32_t myMBH = MBH + mw * 8;       // this warp's h chunk barrier

    for (int s = 0; s < TT; s++) {
        // wait only for THIS warp's 16-row chunk of h
        mbar_wait(myMBH, (uint32_t)(s & 1));

        // ---- fused 4-matrix split-K GEMM: (64 x 512) x (512 x 32) ----
        float acc[4][4];
#pragma unroll
        for (int mt = 0; mt < 4; mt++)
#pragma unroll
            for (int q = 0; q < 4; q++) acc[mt][q] = 0.f;

#pragma unroll
        for (int ks = 0; ks < 16; ks++) {
            unsigned chunk = (chunk0 + (unsigned)(ks * 2)) ^ rowx;
            unsigned a0, a1, a2, a3;
            ldsm4(a0, a1, a2, a3, rowbase + chunk * 16u);
#pragma unroll
            for (int mt = 0; mt < 4; mt++)
                mma16816(acc[mt], a0, a1, a2, a3, bfr[ks][mt][0], bfr[ks][mt][1]);
        }

        // ---- symmetric exchange: kh=0 sends ri=1 rows, kh=1 sends ri=0 rows ----
        {
            float* dst = &S.rbuf[kh][rb];
            int send_q = (kh == 0) ? 2 : 0;
#pragma unroll
            for (int mt = 0; mt < 4; mt++) {
#pragma unroll
                for (int tt = 0; tt < 2; tt++)
                    dst[(mt * 2 + tt) * 32] = acc[mt][send_q + tt];
            }
        }
        __syncthreads();
        float fac[4][2];
        {
            const float* src = &S.rbuf[kh ^ 1][rb];
            int keep_q = (kh == 0) ? 0 : 2;
#pragma unroll
            for (int mt = 0; mt < 4; mt++) {
#pragma unroll
                for (int tt = 0; tt < 2; tt++)
                    fac[mt][tt] = acc[mt][keep_q + tt] + src[(mt * 2 + tt) * 32];
            }
        }

        // sens/tcx for THIS step (prefetched earlier)
        mbar_wait(MBST + (s & 1) * 8, (uint32_t)((s >> 1) & 1));
        const __half* stp = &S.st[s & 1][0];

        // ---- epilogue: 2 units/thread; direct h publish + direct out STG ----
        {
            char* hbase = (char*)g_hbuf + (size_t)((s + 1) & 1) * (BB * HH * 2);
            float hnv[2];
#pragma unroll
            for (int tt = 0; tt < 2; tt++) {
                int jl = 2 * t + tt;
                float sens = __half2float(stp[bl * 16 + jl]);
                float tc0  = __half2float(stp[bl * 16 + 8 + jl]);
                float ytc = fac[0][tt];
                float yw  = fac[1][tt] + biwv[tt];
                float ym  = fac[2][tt] + bimv[tt];
                float ys  = fac[3][tt] + bisv[tt];
                float xs  = tc0 + ytc;
                float sp  = (xs > 20.f) ? xs : __logf(1.f + __expf(xs));
                float tau = sp + 0.1f;
                float sig = __fdividef(1.f, 1.f + __expf(-ym));
                float inter = yw * sig * __expf(fminf(ys, 50.f));
                float hm = h_master[tt];
                float hn = hm + DT_C * __fdividef(sens + inter - hm, fmaxf(tau, EPS_C));
                h_master[tt] = hn;
                hnv[tt] = hn;
            }
            __half2 pair = __floats2half2_rn(hnv[0], hnv[1]);
            *reinterpret_cast<unsigned*>(hbase + (unsigned)bl * 1024u + pub_chunk_off) =
                *reinterpret_cast<unsigned*>(&pair);
            // direct output write (lanes 0-3 of a row form one 32B segment)
            float* od = out + (size_t)bl * TT * HH + (size_t)s * HH + cta * 8 + 2 * t;
            *reinterpret_cast<float2*>(od) = make_float2(hnv[0], hnv[1]);
        }

        if (s < TT - 1) {
            // ---- decentralized arrive: warp-local sync, lane0 releases its word ----
            __syncwarp();
            unsigned p = (unsigned)((s + 1) & 1);
            if (lane == 0) {
                asm volatile("red.release.gpu.global.add.u32 [%0], %1;"
                             :: "l"(&g_cnt[p * 64 + warp]), "r"(1u) : "memory");
            }
            if (tid == 0) {
                // poll the 8-word sector until all 512 warps arrived
                unsigned target = (unsigned)(((s >> 1) + 1) * NCTA2 * 8);
                const unsigned* base = &g_cnt[p * 64];
                unsigned sum;
                do {
                    sum = 0;
#pragma unroll
                    for (int w = 0; w < 8; w++) {
                        unsigned v;
                        asm volatile("ld.acquire.gpu.global.u32 %0, [%1];"
                                     : "=r"(v) : "l"(base + w) : "memory");
                        sum += v;
                    }
                } while (sum < target);
                // everyone published h_{s+1} AND finished reading st[s&1]:
                // stage h (4 row chunks, chunk 0 first) + st prefetch for s+2
                const char* hsrc = (const char*)g_hbuf + (size_t)((s + 1) & 1) * (BB * HH * 2);
#pragma unroll
                for (int c = 0; c < 4; c++) {
                    MBAR_EXPECT_TX(MBH + c * 8, 16384);
                    bulk_g2s(HSb + (unsigned)c * 16384u, hsrc + c * 16384, 16384, MBH + c * 8);
                }
                if (s + 2 < TT) {
                    uint32_t mb = MBST + (s & 1) * 8;   // buffer (s+2)&1 == s&1
                    MBAR_EXPECT_TX(mb, 2048);
                    bulk_g2s(STb + (unsigned)(s & 1) * 2048u,
                             (const char*)g_st + (((size_t)(s + 2) * 64 + cta) * 2048),
                             2048, mb);
                }
            }
            // no CTA-wide sync: next iteration's mbar_wait gates every warp
        }
    }
}

// ---------------- launch ----------------
extern "C" void kernel_launch(void* const* d_in, const int* in_sizes, int n_in,
                              void* d_out, int out_size) {
    const float* x    = (const float*)d_in[0];
    const float* Wsw  = (const float*)d_in[1];
    const float* bsw  = (const float*)d_in[2];
    const float* Wsm  = (const float*)d_in[3];
    const float* bsm  = (const float*)d_in[4];
    const float* Wss  = (const float*)d_in[5];
    const float* bss  = (const float*)d_in[6];
    const float* Wiw  = (const float*)d_in[7];
    const float* biw  = (const float*)d_in[8];
    const float* Wim  = (const float*)d_in[9];
    const float* bim  = (const float*)d_in[10];
    const float* Wis  = (const float*)d_in[11];
    const float* bis  = (const float*)d_in[12];
    const float* Wtcx = (const float*)d_in[13];
    const float* Wtch = (const float*)d_in[14];
    const float* btc  = (const float*)d_in[15];
    float* out = (float*)d_out;

    cudaFuncSetAttribute(phase1_kernel, cudaFuncAttributeMaxDynamicSharedMemorySize,
                         (int)sizeof(P1Smem));
    cudaFuncSetAttribute(phase2_kernel, cudaFuncAttributeMaxDynamicSharedMemorySize,
                         (int)sizeof(P2Smem));

    dim3 g1(512, 16);
    phase1_kernel<<<g1, 256, sizeof(P1Smem)>>>(x, Wsw, Wsm, Wss, Wtcx, bsw, bsm, bss, btc);

    phase2_kernel<<<NCTA2, THR2, sizeof(P2Smem)>>>(out, Wtch, Wiw, Wim, Wis, biw, bim, bis);
}

// round 16
// speedup vs baseline: 1.6045x; 1.6045x over previous
#include <cuda_runtime.h>
#include <cuda_fp16.h>
#include <cstdint>

#define BB 64
#define TT 1024
#define II 128
#define HH 512

static constexpr int   NCTA2 = 64;
static constexpr int   THR2  = 256;   // 8 warps: 2 k-halves x 4 m-tiles
static constexpr float DT_C  = 0.1f;
static constexpr float EPS_C = 1e-8f;

// ---------------- device scratch ----------------
// g_st: per step t, per CTA jb, per batch b: 8 sens + 8 tcx halves (contiguous 2KB per (t,jb))
__device__ __align__(16)  __half g_st[(size_t)TT * 64 * 64 * 16];
// g_hbuf: ping-pong h, SWIZZLED image: row b (1024B), 16B chunk c stored at chunk (c ^ (b&7))
__device__ __align__(128) __half g_hbuf[2 * BB * HH];    // 2 x 64 KB
// single-hop ping-pong barrier counters (one per h-buffer parity), monotonic per call
__device__ __align__(256) unsigned g_cnt[2 * 64];        // [0] and [64] used, padded apart
__device__ unsigned g_bar;   // kept for phase1 reset symmetry (unused)

// ---------------- helpers ----------------
__device__ __forceinline__ unsigned smem_u32(const void* p) {
    return (unsigned)__cvta_generic_to_shared(p);
}
__device__ __forceinline__ void mma16816(float* c,
                                         unsigned a0, unsigned a1, unsigned a2, unsigned a3,
                                         unsigned b0, unsigned b1) {
    asm volatile(
        "mma.sync.aligned.m16n8k16.row.col.f32.f16.f16.f32 "
        "{%0,%1,%2,%3},{%4,%5,%6,%7},{%8,%9},{%0,%1,%2,%3};\n"
        : "+f"(c[0]), "+f"(c[1]), "+f"(c[2]), "+f"(c[3])
        : "r"(a0), "r"(a1), "r"(a2), "r"(a3), "r"(b0), "r"(b1));
}
__device__ __forceinline__ void ldsm4(unsigned& r0, unsigned& r1, unsigned& r2, unsigned& r3,
                                      unsigned addr) {
    asm volatile("ldmatrix.sync.aligned.m8n8.x4.shared.b16 {%0,%1,%2,%3},[%4];\n"
                 : "=r"(r0), "=r"(r1), "=r"(r2), "=r"(r3) : "r"(addr));
}
__device__ __forceinline__ uint4 pack8f(float4 f0, float4 f1) {
    __half2 h0 = __floats2half2_rn(f0.x, f0.y), h1 = __floats2half2_rn(f0.z, f0.w);
    __half2 h2 = __floats2half2_rn(f1.x, f1.y), h3 = __floats2half2_rn(f1.z, f1.w);
    uint4 pv;
    pv.x = *reinterpret_cast<unsigned*>(&h0); pv.y = *reinterpret_cast<unsigned*>(&h1);
    pv.z = *reinterpret_cast<unsigned*>(&h2); pv.w = *reinterpret_cast<unsigned*>(&h3);
    return pv;
}
__device__ __forceinline__ void bulk_g2s(uint32_t dst, const void* src, uint32_t bytes,
                                         uint32_t mbar) {
    asm volatile(
        "cp.async.bulk.shared::cluster.global.mbarrier::complete_tx::bytes [%0], [%1], %2, [%3];\n"
        :: "r"(dst), "l"(src), "r"(bytes), "r"(mbar) : "memory");
}
#define MBAR_INIT(a, n) \
    asm volatile("mbarrier.init.shared.b64 [%0], %1;" :: "r"(a), "r"((unsigned)(n)) : "memory")
#define MBAR_EXPECT_TX(a, n) \
    asm volatile("mbarrier.arrive.expect_tx.shared.b64 _, [%0], %1;" :: "r"(a), "r"((unsigned)(n)) : "memory")
__device__ __forceinline__ void mbar_wait(uint32_t a, uint32_t parity) {
    asm volatile(
        "{\n\t.reg .pred P1;\n\t"
        "WAIT_LOOP_%=:\n\t"
        "mbarrier.try_wait.parity.acquire.cta.shared::cta.b64 P1, [%0], %1, 0x989680;\n\t"
        "@P1 bra.uni WAIT_DONE_%=;\n\t"
        "bra.uni WAIT_LOOP_%=;\n\t"
        "WAIT_DONE_%=:\n\t}"
        :: "r"(a), "r"(parity) : "memory");
}
#define FENCE_PROXY_ASYNC_FULL() asm volatile("fence.proxy.async;" ::: "memory")

// ---------------- phase 1: input projections -> g_st ----------------
#define P1_PITCH 136
struct P1Smem {
    __half A[128 * P1_PITCH];
    __half W[128 * P1_PITCH];
    __half sens[128 * 32];
    __half tcx[128 * 32];
};

__global__ void phase1_kernel(const float* __restrict__ x,
                              const float* __restrict__ Wsw, const float* __restrict__ Wsm,
                              const float* __restrict__ Wss, const float* __restrict__ Wtcx,
                              const float* __restrict__ bsw, const float* __restrict__ bsm,
                              const float* __restrict__ bss, const float* __restrict__ btc) {
    extern __shared__ char smem_raw[];
    P1Smem& S = *reinterpret_cast<P1Smem*>(smem_raw);
    const int tid = threadIdx.x;
    const int m0 = blockIdx.x * 128;
    const int j0 = blockIdx.y * 32;

    // block (0,0): reset barrier counters + init h0 image (buffer 0) to ones
    if (blockIdx.x == 0 && blockIdx.y == 0) {
        if (tid == 0) { g_cnt[0] = 0; g_cnt[64] = 0; g_bar = 0; }
        uint4 ones = make_uint4(0x3C003C00u, 0x3C003C00u, 0x3C003C00u, 0x3C003C00u);
        for (int i = tid; i < BB * HH / 8; i += 256)
            *reinterpret_cast<uint4*>(&g_hbuf[i * 8]) = ones;
    }

    for (int i = tid; i < 128 * 16; i += 256) {
        int r = i >> 4, c = i & 15;
        const float4* src = reinterpret_cast<const float4*>(x + (size_t)(m0 + r) * II + c * 8);
        *reinterpret_cast<uint4*>(&S.A[r * P1_PITCH + c * 8]) = pack8f(src[0], src[1]);
    }
    const float* Wp[4] = { Wsw, Wsm, Wss, Wtcx };
    for (int i = tid; i < 128 * 16; i += 256) {
        int r = i >> 4, c = i & 15;
        int mat = r >> 5, jj = r & 31;
        const float4* src = reinterpret_cast<const float4*>(Wp[mat] + (size_t)(j0 + jj) * II + c * 8);
        *reinterpret_cast<uint4*>(&S.W[r * P1_PITCH + c * 8]) = pack8f(src[0], src[1]);
    }
    __syncthreads();

    const int lane = tid & 31, warp = tid >> 5;
    const int g = lane >> 2, t = lane & 3;
    float acc[16][4];
#pragma unroll
    for (int nt = 0; nt < 16; nt++)
#pragma unroll
        for (int q = 0; q < 4; q++) acc[nt][q] = 0.f;

    const int ar0 = (warp * 16 + g) * P1_PITCH;
    const int ar1 = (warp * 16 + g + 8) * P1_PITCH;
#pragma unroll
    for (int ks = 0; ks < 8; ks++) {
        const int k0 = ks * 16 + 2 * t;
        unsigned a0 = *reinterpret_cast<unsigned*>(&S.A[ar0 + k0]);
        unsigned a1 = *reinterpret_cast<unsigned*>(&S.A[ar1 + k0]);
        unsigned a2 = *reinterpret_cast<unsigned*>(&S.A[ar0 + k0 + 8]);
        unsigned a3 = *reinterpret_cast<unsigned*>(&S.A[ar1 + k0 + 8]);
#pragma unroll
        for (int nt = 0; nt < 16; nt++) {
            unsigned b0 = *reinterpret_cast<unsigned*>(&S.W[(nt * 8 + g) * P1_PITCH + k0]);
            unsigned b1 = *reinterpret_cast<unsigned*>(&S.W[(nt * 8 + g) * P1_PITCH + k0 + 8]);
            mma16816(acc[nt], a0, a1, a2, a3, b0, b1);
        }
    }

#pragma unroll
    for (int jb = 0; jb < 4; jb++) {
#pragma unroll
        for (int ri = 0; ri < 2; ri++) {
#pragma unroll
            for (int tt = 0; tt < 2; tt++) {
                int q = ri * 2 + tt;
                int jl = jb * 8 + 2 * t + tt;
                int jg = j0 + jl;
                float sw   = acc[0 * 4 + jb][q] + bsw[jg];
                float smu  = acc[1 * 4 + jb][q] + bsm[jg];
                float ssig = acc[2 * 4 + jb][q] + bss[jg];
                float tc   = acc[3 * 4 + jb][q] + btc[jg];
                float sig  = __fdividef(1.f, 1.f + __expf(-smu));
                float sens = sw * sig * __expf(fminf(ssig, 50.f));
                int ml = warp * 16 + g + ri * 8;
                S.sens[ml * 32 + jl] = __float2half(sens);
                S.tcx [ml * 32 + jl] = __float2half(tc);
            }
        }
    }
    __syncthreads();

    // write-out: g_st[t][jb][b][0:8]=sens, [8:16]=tcx
    {
        int r = tid & 127;
        int m = m0 + r;
        int b = m >> 10, tm = m & 1023;
        int jb0 = j0 >> 3;
#pragma unroll
        for (int jbl = 0; jbl < 4; jbl++) {
            size_t dst = (((size_t)tm * 64 + jb0 + jbl) * 64 + b) * 16;
            if (tid < 128) {
                *reinterpret_cast<uint4*>(g_st + dst) =
                    *reinterpret_cast<const uint4*>(&S.sens[r * 32 + jbl * 8]);
            } else {
                *reinterpret_cast<uint4*>(g_st + dst + 8) =
                    *reinterpret_cast<const uint4*>(&S.tcx[r * 32 + jbl * 8]);
            }
        }
    }
}

// ---------------- phase 2: recurrence ----------------
// Round-14 winner structure: 4 row-chunked 16KB h bulks (warp kh*4+mw waits only
// on chunk mw), single-hop single-word barrier (one RED per CTA), symmetric
// split-K exchange, direct h publish from epilogue, out STGs overlap the spin.
// Delta vs round 14: poll uses ld.relaxed, one ld.acquire confirm.
#define WST_PITCH 520
struct P2Smem {
    __half  Hs[BB * HH];         // 64KB linear (row b: 1024B, chunks XOR-swizzled)
    __half  Wst[32 * WST_PITCH]; // one-time weight staging
    __half  st[2][64 * 16];      // sens/tcx double buffer (bulk dst)
    float   outs[64 * 8];
    float   rbuf[2][4 * 8 * 32]; // split-K partials: [src kh][(mw*8+mt*2+tt)*32+lane]
    unsigned long long mb_h[4];  // per-row-chunk h barriers
    unsigned long long mb_st[2]; // sens/tcx prefetch barriers
};

__global__ void __launch_bounds__(THR2, 1)
phase2_kernel(float* __restrict__ out,
              const float* __restrict__ Wtch, const float* __restrict__ Wiw,
              const float* __restrict__ Wim,  const float* __restrict__ Wis,
              const float* __restrict__ biw, const float* __restrict__ bim,
              const float* __restrict__ bis) {
    extern __shared__ char smem_raw[];
    P2Smem& S = *reinterpret_cast<P2Smem*>(smem_raw);
    const int tid  = threadIdx.x;
    const int cta  = blockIdx.x;
    const int lane = tid & 31, warp = tid >> 5;
    const int mw = warp & 3, kh = warp >> 2;
    const int g = lane >> 2, t = lane & 3;

    const uint32_t HSb  = smem_u32(&S.Hs[0]);
    const uint32_t STb  = smem_u32(&S.st[0][0]);
    const uint32_t MBH  = smem_u32(&S.mb_h[0]);
    const uint32_t MBST = smem_u32(&S.mb_st[0]);

    // ---- one-time: stage weights (fp32 -> fp16) and preload B frags ----
    const float* Wp[4] = { Wtch, Wiw, Wim, Wis };
    for (int i = tid; i < 32 * 64; i += THR2) {
        int r = i >> 6, c8 = (i & 63) * 8;
        int mat = r >> 3, jj = r & 7;
        const float4* src = reinterpret_cast<const float4*>(
            Wp[mat] + (size_t)(cta * 8 + jj) * HH + c8);
        *reinterpret_cast<uint4*>(&S.Wst[r * WST_PITCH + c8]) = pack8f(src[0], src[1]);
    }
    if (tid == 0) {
#pragma unroll
        for (int c = 0; c < 4; c++) MBAR_INIT(MBH + c * 8, 1);
        MBAR_INIT(MBST + 0, 1);
        MBAR_INIT(MBST + 8, 1);
    }
    __syncthreads();
    FENCE_PROXY_ASYNC_FULL();   // one-time: mbarrier/SMEM init visible to async proxy
    __syncthreads();

    // preamble: issue h(step0) as 4 chunks + st(step0) + st(step1)
    if (tid == 0) {
#pragma unroll
        for (int c = 0; c < 4; c++) {
            MBAR_EXPECT_TX(MBH + c * 8, 16384);
            bulk_g2s(HSb + (unsigned)c * 16384u, (const char*)g_hbuf + c * 16384,
                     16384, MBH + c * 8);
        }
        MBAR_EXPECT_TX(MBST + 0, 2048);
        bulk_g2s(STb, (const char*)g_st + ((size_t)cta * 2048), 2048, MBST + 0);
        MBAR_EXPECT_TX(MBST + 8, 2048);
        bulk_g2s(STb + 2048u, (const char*)g_st + (((size_t)64 + cta) * 2048), 2048, MBST + 8);
    }

    unsigned bfr[16][4][2];
#pragma unroll
    for (int ks = 0; ks < 16; ks++) {
        const int k0 = kh * 256 + ks * 16 + 2 * t;
#pragma unroll
        for (int mt = 0; mt < 4; mt++) {
            bfr[ks][mt][0] = *reinterpret_cast<unsigned*>(&S.Wst[(mt * 8 + g) * WST_PITCH + k0]);
            bfr[ks][mt][1] = *reinterpret_cast<unsigned*>(&S.Wst[(mt * 8 + g) * WST_PITCH + k0 + 8]);
        }
    }

    float biwv[2], bimv[2], bisv[2];
    {
        int jg = cta * 8 + 2 * t;
        biwv[0] = biw[jg]; biwv[1] = biw[jg + 1];
        bimv[0] = bim[jg]; bimv[1] = bim[jg + 1];
        bisv[0] = bis[jg]; bisv[1] = bis[jg + 1];
    }
    // this thread's epilogue row/units: row bl = mw*16 + g + kh*8, units 2t/2t+1
    const int bl = mw * 16 + g + kh * 8;
    float h_master[2];
    h_master[0] = 1.0f; h_master[1] = 1.0f;

    // ldmatrix addressing (swizzled): row = mw*16 + (lane&15)
    const int arow   = mw * 16 + (lane & 15);
    const unsigned rowbase = HSb + (unsigned)arow * 1024u;
    const unsigned rowx    = (unsigned)(arow & 7);
    const unsigned chunk0  = (unsigned)(kh * 32 + (lane >> 4));
    const unsigned pub_chunk_off = ((unsigned)(cta ^ g)) * 16u + (unsigned)t * 4u;
    const int rb = (mw * 8 + 0) * 32 + lane;   // base rbuf slot (mt=0, tt=0)
    const uint32_t myMBH = MBH + mw * 8;       // this warp's h chunk barrier

    for (int s = 0; s < TT; s++) {
        // wait only for THIS warp's 16-row chunk of h
        mbar_wait(myMBH, (uint32_t)(s & 1));

        // ---- fused 4-matrix split-K GEMM: (64 x 512) x (512 x 32) ----
        float acc[4][4];
#pragma unroll
        for (int mt = 0; mt < 4; mt++)
#pragma unroll
            for (int q = 0; q < 4; q++) acc[mt][q] = 0.f;

#pragma unroll
        for (int ks = 0; ks < 16; ks++) {
            unsigned chunk = (chunk0 + (unsigned)(ks * 2)) ^ rowx;
            unsigned a0, a1, a2, a3;
            ldsm4(a0, a1, a2, a3, rowbase + chunk * 16u);
#pragma unroll
            for (int mt = 0; mt < 4; mt++)
                mma16816(acc[mt], a0, a1, a2, a3, bfr[ks][mt][0], bfr[ks][mt][1]);
        }

        // ---- symmetric exchange: kh=0 sends ri=1 rows, kh=1 sends ri=0 rows ----
        {
            float* dst = &S.rbuf[kh][rb];
            int send_q = (kh == 0) ? 2 : 0;
#pragma unroll
            for (int mt = 0; mt < 4; mt++) {
#pragma unroll
                for (int tt = 0; tt < 2; tt++)
                    dst[(mt * 2 + tt) * 32] = acc[mt][send_q + tt];
            }
        }
        __syncthreads();
        float fac[4][2];
        {
            const float* src = &S.rbuf[kh ^ 1][rb];
            int keep_q = (kh == 0) ? 0 : 2;
#pragma unroll
            for (int mt = 0; mt < 4; mt++) {
#pragma unroll
                for (int tt = 0; tt < 2; tt++)
                    fac[mt][tt] = acc[mt][keep_q + tt] + src[(mt * 2 + tt) * 32];
            }
        }

        // sens/tcx for THIS step (prefetched earlier)
        mbar_wait(MBST + (s & 1) * 8, (uint32_t)((s >> 1) & 1));
        const __half* stp = &S.st[s & 1][0];

        // ---- epilogue: 2 units/thread, direct h publish ----
        {
            char* hbase = (char*)g_hbuf + (size_t)((s + 1) & 1) * (BB * HH * 2);
            float hnv[2];
#pragma unroll
            for (int tt = 0; tt < 2; tt++) {
                int jl = 2 * t + tt;
                float sens = __half2float(stp[bl * 16 + jl]);
                float tc0  = __half2float(stp[bl * 16 + 8 + jl]);
                float ytc = fac[0][tt];
                float yw  = fac[1][tt] + biwv[tt];
                float ym  = fac[2][tt] + bimv[tt];
                float ys  = fac[3][tt] + bisv[tt];
                float xs  = tc0 + ytc;
                float sp  = (xs > 20.f) ? xs : __logf(1.f + __expf(xs));
                float tau = sp + 0.1f;
                float sig = __fdividef(1.f, 1.f + __expf(-ym));
                float inter = yw * sig * __expf(fminf(ys, 50.f));
                float hm = h_master[tt];
                float hn = hm + DT_C * __fdividef(sens + inter - hm, fmaxf(tau, EPS_C));
                h_master[tt] = hn;
                hnv[tt] = hn;
                S.outs[bl * 8 + jl] = hn;
            }
            __half2 pair = __floats2half2_rn(hnv[0], hnv[1]);
            *reinterpret_cast<unsigned*>(hbase + (unsigned)bl * 1024u + pub_chunk_off) =
                *reinterpret_cast<unsigned*>(&pair);
        }
        __syncthreads();   // epilogue + publishes done CTA-wide

        if (s < TT - 1) {
            if (tid == 0) {
                // prefetch st (static data, no ordering needed) BEFORE the barrier
                if (s + 2 < TT) {
                    uint32_t mb = MBST + (s & 1) * 8;   // buffer (s+2)&1 == s&1
                    MBAR_EXPECT_TX(mb, 2048);
                    bulk_g2s(STb + (unsigned)(s & 1) * 2048u,
                             (const char*)g_st + (((size_t)(s + 2) * 64 + cta) * 2048),
                             2048, mb);
                }
                // single-hop barrier: fire-and-forget arrive, relaxed poll + acquire confirm
                unsigned* cnt = &g_cnt[((s + 1) & 1) * 64];
                asm volatile("red.release.gpu.global.add.u32 [%0], %1;"
                             :: "l"(cnt), "r"(1u) : "memory");
                unsigned target = (unsigned)(((s >> 1) + 1) * NCTA2);
                unsigned v;
                for (;;) {
                    asm volatile("ld.relaxed.gpu.global.u32 %0, [%1];"
                                 : "=r"(v) : "l"(cnt) : "memory");
                    if (v >= target) {
                        asm volatile("ld.acquire.gpu.global.u32 %0, [%1];"
                                     : "=r"(v) : "l"(cnt) : "memory");
                        if (v >= target) break;
                    }
                }
                // all 64 CTAs published h_{s+1} -> stage it in 4 row chunks (0 first)
                const char* hsrc = (const char*)g_hbuf + (size_t)((s + 1) & 1) * (BB * HH * 2);
#pragma unroll
                for (int c = 0; c < 4; c++) {
                    MBAR_EXPECT_TX(MBH + c * 8, 16384);
                    bulk_g2s(HSb + (unsigned)c * 16384u, hsrc + c * 16384, 16384, MBH + c * 8);
                }
            } else if (tid >= 128) {
                // overlap barrier latency with output writes
                int u = tid - 128;
                int r = u >> 1, part = u & 1;
                float* od = out + (size_t)r * TT * HH + (size_t)s * HH + cta * 8 + part * 4;
                *reinterpret_cast<uint4*>(od) =
                    *reinterpret_cast<const uint4*>(&S.outs[r * 8 + part * 4]);
            }
            // no post-barrier sync: next iteration's mbar_wait gates everything
        } else {
            if (tid >= 128) {
                int u = tid - 128;
                int r = u >> 1, part = u & 1;
                float* od = out + (size_t)r * TT * HH + (size_t)s * HH + cta * 8 + part * 4;
                *reinterpret_cast<uint4*>(od) =
                    *reinterpret_cast<const uint4*>(&S.outs[r * 8 + part * 4]);
            }
        }
    }
}

// ---------------- launch ----------------
extern "C" void kernel_launch(void* const* d_in, const int* in_sizes, int n_in,
                              void* d_out, int out_size) {
    const float* x    = (const float*)d_in[0];
    const float* Wsw  = (const float*)d_in[1];
    const float* bsw  = (const float*)d_in[2];
    const float* Wsm  = (const float*)d_in[3];
    const float* bsm  = (const float*)d_in[4];
    const float* Wss  = (const float*)d_in[5];
    const float* bss  = (const float*)d_in[6];
    const float* Wiw  = (const float*)d_in[7];
    const float* biw  = (const float*)d_in[8];
    const float* Wim  = (const float*)d_in[9];
    const float* bim  = (const float*)d_in[10];
    const float* Wis  = (const float*)d_in[11];
    const float* bis  = (const float*)d_in[12];
    const float* Wtcx = (const float*)d_in[13];
    const float* Wtch = (const float*)d_in[14];
    const float* btc  = (const float*)d_in[15];
    float* out = (float*)d_out;

    cudaFuncSetAttribute(phase1_kernel, cudaFuncAttributeMaxDynamicSharedMemorySize,
                         (int)sizeof(P1Smem));
    cudaFuncSetAttribute(phase2_kernel, cudaFuncAttributeMaxDynamicSharedMemorySize,
                         (int)sizeof(P2Smem));

    dim3 g1(512, 16);
    phase1_kernel<<<g1, 256, sizeof(P1Smem)>>>(x, Wsw, Wsm, Wss, Wtcx, bsw, bsm, bss, btc);

    phase2_kernel<<<NCTA2, THR2, sizeof(P2Smem)>>>(out, Wtch, Wiw, Wim, Wis, biw, bim, bis);
}

// round 17
// speedup vs baseline: 1.7192x; 1.0714x over previous
#include <cuda_runtime.h>
#include <cuda_fp16.h>
#include <cstdint>

#define BB 64
#define TT 1024
#define II 128
#define HH 512

static constexpr int   NCTA2 = 64;
static constexpr int   THR2  = 256;   // 8 warps: 2 k-halves x 4 m-tiles
static constexpr float DT_C  = 0.1f;
static constexpr float EPS_C = 1e-8f;

// ---------------- device scratch ----------------
// g_st: per step t, per CTA jb, per batch b: 8 sens + 8 tcx halves (contiguous 2KB per (t,jb))
__device__ __align__(16)  __half g_st[(size_t)TT * 64 * 64 * 16];
// g_hbuf: ping-pong h, SWIZZLED image: row b (1024B), 16B chunk c stored at chunk (c ^ (b&7))
__device__ __align__(128) __half g_hbuf[2 * BB * HH];    // 2 x 64 KB
// single-hop ping-pong barrier counters (one per h-buffer parity), monotonic per call
__device__ __align__(256) unsigned g_cnt[2 * 64];        // [0] and [64] used, padded apart
__device__ unsigned g_bar;   // kept for phase1 reset symmetry (unused)

// ---------------- helpers ----------------
__device__ __forceinline__ unsigned smem_u32(const void* p) {
    return (unsigned)__cvta_generic_to_shared(p);
}
__device__ __forceinline__ void mma16816(float* c,
                                         unsigned a0, unsigned a1, unsigned a2, unsigned a3,
                                         unsigned b0, unsigned b1) {
    asm volatile(
        "mma.sync.aligned.m16n8k16.row.col.f32.f16.f16.f32 "
        "{%0,%1,%2,%3},{%4,%5,%6,%7},{%8,%9},{%0,%1,%2,%3};\n"
        : "+f"(c[0]), "+f"(c[1]), "+f"(c[2]), "+f"(c[3])
        : "r"(a0), "r"(a1), "r"(a2), "r"(a3), "r"(b0), "r"(b1));
}
__device__ __forceinline__ void ldsm4(unsigned& r0, unsigned& r1, unsigned& r2, unsigned& r3,
                                      unsigned addr) {
    asm volatile("ldmatrix.sync.aligned.m8n8.x4.shared.b16 {%0,%1,%2,%3},[%4];\n"
                 : "=r"(r0), "=r"(r1), "=r"(r2), "=r"(r3) : "r"(addr));
}
__device__ __forceinline__ uint4 pack8f(float4 f0, float4 f1) {
    __half2 h0 = __floats2half2_rn(f0.x, f0.y), h1 = __floats2half2_rn(f0.z, f0.w);
    __half2 h2 = __floats2half2_rn(f1.x, f1.y), h3 = __floats2half2_rn(f1.z, f1.w);
    uint4 pv;
    pv.x = *reinterpret_cast<unsigned*>(&h0); pv.y = *reinterpret_cast<unsigned*>(&h1);
    pv.z = *reinterpret_cast<unsigned*>(&h2); pv.w = *reinterpret_cast<unsigned*>(&h3);
    return pv;
}
__device__ __forceinline__ void bulk_g2s(uint32_t dst, const void* src, uint32_t bytes,
                                         uint32_t mbar) {
    asm volatile(
        "cp.async.bulk.shared::cluster.global.mbarrier::complete_tx::bytes [%0], [%1], %2, [%3];\n"
        :: "r"(dst), "l"(src), "r"(bytes), "r"(mbar) : "memory");
}
#define MBAR_INIT(a, n) \
    asm volatile("mbarrier.init.shared.b64 [%0], %1;" :: "r"(a), "r"((unsigned)(n)) : "memory")
#define MBAR_EXPECT_TX(a, n) \
    asm volatile("mbarrier.arrive.expect_tx.shared.b64 _, [%0], %1;" :: "r"(a), "r"((unsigned)(n)) : "memory")
__device__ __forceinline__ void mbar_wait(uint32_t a, uint32_t parity) {
    asm volatile(
        "{\n\t.reg .pred P1;\n\t"
        "WAIT_LOOP_%=:\n\t"
        "mbarrier.try_wait.parity.acquire.cta.shared::cta.b64 P1, [%0], %1, 0x989680;\n\t"
        "@P1 bra.uni WAIT_DONE_%=;\n\t"
        "bra.uni WAIT_LOOP_%=;\n\t"
        "WAIT_DONE_%=:\n\t}"
        :: "r"(a), "r"(parity) : "memory");
}
#define FENCE_PROXY_ASYNC_FULL() asm volatile("fence.proxy.async;" ::: "memory")

// ---------------- phase 1: input projections -> g_st ----------------
#define P1_PITCH 136
struct P1Smem {
    __half A[128 * P1_PITCH];
    __half W[128 * P1_PITCH];
    __half sens[128 * 32];
    __half tcx[128 * 32];
};

__global__ void phase1_kernel(const float* __restrict__ x,
                              const float* __restrict__ Wsw, const float* __restrict__ Wsm,
                              const float* __restrict__ Wss, const float* __restrict__ Wtcx,
                              const float* __restrict__ bsw, const float* __restrict__ bsm,
                              const float* __restrict__ bss, const float* __restrict__ btc) {
    extern __shared__ char smem_raw[];
    P1Smem& S = *reinterpret_cast<P1Smem*>(smem_raw);
    const int tid = threadIdx.x;
    const int m0 = blockIdx.x * 128;
    const int j0 = blockIdx.y * 32;

    // block (0,0): reset barrier counters + init h0 image (buffer 0) to ones
    if (blockIdx.x == 0 && blockIdx.y == 0) {
        if (tid == 0) { g_cnt[0] = 0; g_cnt[64] = 0; g_bar = 0; }
        uint4 ones = make_uint4(0x3C003C00u, 0x3C003C00u, 0x3C003C00u, 0x3C003C00u);
        for (int i = tid; i < BB * HH / 8; i += 256)
            *reinterpret_cast<uint4*>(&g_hbuf[i * 8]) = ones;
    }

    for (int i = tid; i < 128 * 16; i += 256) {
        int r = i >> 4, c = i & 15;
        const float4* src = reinterpret_cast<const float4*>(x + (size_t)(m0 + r) * II + c * 8);
        *reinterpret_cast<uint4*>(&S.A[r * P1_PITCH + c * 8]) = pack8f(src[0], src[1]);
    }
    const float* Wp[4] = { Wsw, Wsm, Wss, Wtcx };
    for (int i = tid; i < 128 * 16; i += 256) {
        int r = i >> 4, c = i & 15;
        int mat = r >> 5, jj = r & 31;
        const float4* src = reinterpret_cast<const float4*>(Wp[mat] + (size_t)(j0 + jj) * II + c * 8);
        *reinterpret_cast<uint4*>(&S.W[r * P1_PITCH + c * 8]) = pack8f(src[0], src[1]);
    }
    __syncthreads();

    const int lane = tid & 31, warp = tid >> 5;
    const int g = lane >> 2, t = lane & 3;
    float acc[16][4];
#pragma unroll
    for (int nt = 0; nt < 16; nt++)
#pragma unroll
        for (int q = 0; q < 4; q++) acc[nt][q] = 0.f;

    const int ar0 = (warp * 16 + g) * P1_PITCH;
    const int ar1 = (warp * 16 + g + 8) * P1_PITCH;
#pragma unroll
    for (int ks = 0; ks < 8; ks++) {
        const int k0 = ks * 16 + 2 * t;
        unsigned a0 = *reinterpret_cast<unsigned*>(&S.A[ar0 + k0]);
        unsigned a1 = *reinterpret_cast<unsigned*>(&S.A[ar1 + k0]);
        unsigned a2 = *reinterpret_cast<unsigned*>(&S.A[ar0 + k0 + 8]);
        unsigned a3 = *reinterpret_cast<unsigned*>(&S.A[ar1 + k0 + 8]);
#pragma unroll
        for (int nt = 0; nt < 16; nt++) {
            unsigned b0 = *reinterpret_cast<unsigned*>(&S.W[(nt * 8 + g) * P1_PITCH + k0]);
            unsigned b1 = *reinterpret_cast<unsigned*>(&S.W[(nt * 8 + g) * P1_PITCH + k0 + 8]);
            mma16816(acc[nt], a0, a1, a2, a3, b0, b1);
        }
    }

#pragma unroll
    for (int jb = 0; jb < 4; jb++) {
#pragma unroll
        for (int ri = 0; ri < 2; ri++) {
#pragma unroll
            for (int tt = 0; tt < 2; tt++) {
                int q = ri * 2 + tt;
                int jl = jb * 8 + 2 * t + tt;
                int jg = j0 + jl;
                float sw   = acc[0 * 4 + jb][q] + bsw[jg];
                float smu  = acc[1 * 4 + jb][q] + bsm[jg];
                float ssig = acc[2 * 4 + jb][q] + bss[jg];
                float tc   = acc[3 * 4 + jb][q] + btc[jg];
                float sig  = __fdividef(1.f, 1.f + __expf(-smu));
                float sens = sw * sig * __expf(fminf(ssig, 50.f));
                int ml = warp * 16 + g + ri * 8;
                S.sens[ml * 32 + jl] = __float2half(sens);
                S.tcx [ml * 32 + jl] = __float2half(tc);
            }
        }
    }
    __syncthreads();

    // write-out: g_st[t][jb][b][0:8]=sens, [8:16]=tcx
    {
        int r = tid & 127;
        int m = m0 + r;
        int b = m >> 10, tm = m & 1023;
        int jb0 = j0 >> 3;
#pragma unroll
        for (int jbl = 0; jbl < 4; jbl++) {
            size_t dst = (((size_t)tm * 64 + jb0 + jbl) * 64 + b) * 16;
            if (tid < 128) {
                *reinterpret_cast<uint4*>(g_st + dst) =
                    *reinterpret_cast<const uint4*>(&S.sens[r * 32 + jbl * 8]);
            } else {
                *reinterpret_cast<uint4*>(g_st + dst + 8) =
                    *reinterpret_cast<const uint4*>(&S.tcx[r * 32 + jbl * 8]);
            }
        }
    }
}

// ---------------- phase 2: recurrence ----------------
// Round-14 winner structure: 4 row-chunked 16KB h bulks (warp kh*4+mw waits only
// on chunk mw), single-hop single-word barrier (one RED per CTA, pure acquire
// poll), symmetric split-K exchange, direct h publish from epilogue, out STGs
// overlap the spin. Delta vs round 14: MBST wait + sens/tcx LDS hoisted above
// the exchange __syncthreads (off the post-sync critical path).
#define WST_PITCH 520
struct P2Smem {
    __half  Hs[BB * HH];         // 64KB linear (row b: 1024B, chunks XOR-swizzled)
    __half  Wst[32 * WST_PITCH]; // one-time weight staging
    __half  st[2][64 * 16];      // sens/tcx double buffer (bulk dst)
    float   outs[64 * 8];
    float   rbuf[2][4 * 8 * 32]; // split-K partials: [src kh][(mw*8+mt*2+tt)*32+lane]
    unsigned long long mb_h[4];  // per-row-chunk h barriers
    unsigned long long mb_st[2]; // sens/tcx prefetch barriers
};

__global__ void __launch_bounds__(THR2, 1)
phase2_kernel(float* __restrict__ out,
              const float* __restrict__ Wtch, const float* __restrict__ Wiw,
              const float* __restrict__ Wim,  const float* __restrict__ Wis,
              const float* __restrict__ biw, const float* __restrict__ bim,
              const float* __restrict__ bis) {
    extern __shared__ char smem_raw[];
    P2Smem& S = *reinterpret_cast<P2Smem*>(smem_raw);
    const int tid  = threadIdx.x;
    const int cta  = blockIdx.x;
    const int lane = tid & 31, warp = tid >> 5;
    const int mw = warp & 3, kh = warp >> 2;
    const int g = lane >> 2, t = lane & 3;

    const uint32_t HSb  = smem_u32(&S.Hs[0]);
    const uint32_t STb  = smem_u32(&S.st[0][0]);
    const uint32_t MBH  = smem_u32(&S.mb_h[0]);
    const uint32_t MBST = smem_u32(&S.mb_st[0]);

    // ---- one-time: stage weights (fp32 -> fp16) and preload B frags ----
    const float* Wp[4] = { Wtch, Wiw, Wim, Wis };
    for (int i = tid; i < 32 * 64; i += THR2) {
        int r = i >> 6, c8 = (i & 63) * 8;
        int mat = r >> 3, jj = r & 7;
        const float4* src = reinterpret_cast<const float4*>(
            Wp[mat] + (size_t)(cta * 8 + jj) * HH + c8);
        *reinterpret_cast<uint4*>(&S.Wst[r * WST_PITCH + c8]) = pack8f(src[0], src[1]);
    }
    if (tid == 0) {
#pragma unroll
        for (int c = 0; c < 4; c++) MBAR_INIT(MBH + c * 8, 1);
        MBAR_INIT(MBST + 0, 1);
        MBAR_INIT(MBST + 8, 1);
    }
    __syncthreads();
    FENCE_PROXY_ASYNC_FULL();   // one-time: mbarrier/SMEM init visible to async proxy
    __syncthreads();

    // preamble: issue h(step0) as 4 chunks + st(step0) + st(step1)
    if (tid == 0) {
#pragma unroll
        for (int c = 0; c < 4; c++) {
            MBAR_EXPECT_TX(MBH + c * 8, 16384);
            bulk_g2s(HSb + (unsigned)c * 16384u, (const char*)g_hbuf + c * 16384,
                     16384, MBH + c * 8);
        }
        MBAR_EXPECT_TX(MBST + 0, 2048);
        bulk_g2s(STb, (const char*)g_st + ((size_t)cta * 2048), 2048, MBST + 0);
        MBAR_EXPECT_TX(MBST + 8, 2048);
        bulk_g2s(STb + 2048u, (const char*)g_st + (((size_t)64 + cta) * 2048), 2048, MBST + 8);
    }

    unsigned bfr[16][4][2];
#pragma unroll
    for (int ks = 0; ks < 16; ks++) {
        const int k0 = kh * 256 + ks * 16 + 2 * t;
#pragma unroll
        for (int mt = 0; mt < 4; mt++) {
            bfr[ks][mt][0] = *reinterpret_cast<unsigned*>(&S.Wst[(mt * 8 + g) * WST_PITCH + k0]);
            bfr[ks][mt][1] = *reinterpret_cast<unsigned*>(&S.Wst[(mt * 8 + g) * WST_PITCH + k0 + 8]);
        }
    }

    float biwv[2], bimv[2], bisv[2];
    {
        int jg = cta * 8 + 2 * t;
        biwv[0] = biw[jg]; biwv[1] = biw[jg + 1];
        bimv[0] = bim[jg]; bimv[1] = bim[jg + 1];
        bisv[0] = bis[jg]; bisv[1] = bis[jg + 1];
    }
    // this thread's epilogue row/units: row bl = mw*16 + g + kh*8, units 2t/2t+1
    const int bl = mw * 16 + g + kh * 8;
    float h_master[2];
    h_master[0] = 1.0f; h_master[1] = 1.0f;

    // ldmatrix addressing (swizzled): row = mw*16 + (lane&15)
    const int arow   = mw * 16 + (lane & 15);
    const unsigned rowbase = HSb + (unsigned)arow * 1024u;
    const unsigned rowx    = (unsigned)(arow & 7);
    const unsigned chunk0  = (unsigned)(kh * 32 + (lane >> 4));
    const unsigned pub_chunk_off = ((unsigned)(cta ^ g)) * 16u + (unsigned)t * 4u;
    const int rb = (mw * 8 + 0) * 32 + lane;   // base rbuf slot (mt=0, tt=0)
    const uint32_t myMBH = MBH + mw * 8;       // this warp's h chunk barrier

    for (int s = 0; s < TT; s++) {
        // wait only for THIS warp's 16-row chunk of h
        mbar_wait(myMBH, (uint32_t)(s & 1));

        // ---- fused 4-matrix split-K GEMM: (64 x 512) x (512 x 32) ----
        float acc[4][4];
#pragma unroll
        for (int mt = 0; mt < 4; mt++)
#pragma unroll
            for (int q = 0; q < 4; q++) acc[mt][q] = 0.f;

#pragma unroll
        for (int ks = 0; ks < 16; ks++) {
            unsigned chunk = (chunk0 + (unsigned)(ks * 2)) ^ rowx;
            unsigned a0, a1, a2, a3;
            ldsm4(a0, a1, a2, a3, rowbase + chunk * 16u);
#pragma unroll
            for (int mt = 0; mt < 4; mt++)
                mma16816(acc[mt], a0, a1, a2, a3, bfr[ks][mt][0], bfr[ks][mt][1]);
        }

        // ---- sens/tcx for THIS step: wait + load BEFORE the exchange sync ----
        mbar_wait(MBST + (s & 1) * 8, (uint32_t)((s >> 1) & 1));
        float sens_r[2], tc_r[2];
        {
            const __half* stp = &S.st[s & 1][0];
#pragma unroll
            for (int tt = 0; tt < 2; tt++) {
                int jl = 2 * t + tt;
                sens_r[tt] = __half2float(stp[bl * 16 + jl]);
                tc_r[tt]   = __half2float(stp[bl * 16 + 8 + jl]);
            }
        }

        // ---- symmetric exchange: kh=0 sends ri=1 rows, kh=1 sends ri=0 rows ----
        {
            float* dst = &S.rbuf[kh][rb];
            int send_q = (kh == 0) ? 2 : 0;
#pragma unroll
            for (int mt = 0; mt < 4; mt++) {
#pragma unroll
                for (int tt = 0; tt < 2; tt++)
                    dst[(mt * 2 + tt) * 32] = acc[mt][send_q + tt];
            }
        }
        __syncthreads();
        float fac[4][2];
        {
            const float* src = &S.rbuf[kh ^ 1][rb];
            int keep_q = (kh == 0) ? 0 : 2;
#pragma unroll
            for (int mt = 0; mt < 4; mt++) {
#pragma unroll
                for (int tt = 0; tt < 2; tt++)
                    fac[mt][tt] = acc[mt][keep_q + tt] + src[(mt * 2 + tt) * 32];
            }
        }

        // ---- epilogue: 2 units/thread, direct h publish ----
        {
            char* hbase = (char*)g_hbuf + (size_t)((s + 1) & 1) * (BB * HH * 2);
            float hnv[2];
#pragma unroll
            for (int tt = 0; tt < 2; tt++) {
                float ytc = fac[0][tt];
                float yw  = fac[1][tt] + biwv[tt];
                float ym  = fac[2][tt] + bimv[tt];
                float ys  = fac[3][tt] + bisv[tt];
                float xs  = tc_r[tt] + ytc;
                float sp  = (xs > 20.f) ? xs : __logf(1.f + __expf(xs));
                float tau = sp + 0.1f;
                float sig = __fdividef(1.f, 1.f + __expf(-ym));
                float inter = yw * sig * __expf(fminf(ys, 50.f));
                float hm = h_master[tt];
                float hn = hm + DT_C * __fdividef(sens_r[tt] + inter - hm, fmaxf(tau, EPS_C));
                h_master[tt] = hn;
                hnv[tt] = hn;
                S.outs[bl * 8 + 2 * t + tt] = hn;
            }
            __half2 pair = __floats2half2_rn(hnv[0], hnv[1]);
            *reinterpret_cast<unsigned*>(hbase + (unsigned)bl * 1024u + pub_chunk_off) =
                *reinterpret_cast<unsigned*>(&pair);
        }
        __syncthreads();   // epilogue + publishes done CTA-wide

        if (s < TT - 1) {
            if (tid == 0) {
                // prefetch st (static data, no ordering needed) BEFORE the barrier
                if (s + 2 < TT) {
                    uint32_t mb = MBST + (s & 1) * 8;   // buffer (s+2)&1 == s&1
                    MBAR_EXPECT_TX(mb, 2048);
                    bulk_g2s(STb + (unsigned)(s & 1) * 2048u,
                             (const char*)g_st + (((size_t)(s + 2) * 64 + cta) * 2048),
                             2048, mb);
                }
                // single-hop barrier: fire-and-forget arrive, acquire poll
                unsigned* cnt = &g_cnt[((s + 1) & 1) * 64];
                asm volatile("red.release.gpu.global.add.u32 [%0], %1;"
                             :: "l"(cnt), "r"(1u) : "memory");
                unsigned target = (unsigned)(((s >> 1) + 1) * NCTA2);
                unsigned v;
                do {
                    asm volatile("ld.acquire.gpu.global.u32 %0, [%1];"
                                 : "=r"(v) : "l"(cnt) : "memory");
                } while (v < target);
                // all 64 CTAs published h_{s+1} -> stage it in 4 row chunks (0 first)
                const char* hsrc = (const char*)g_hbuf + (size_t)((s + 1) & 1) * (BB * HH * 2);
#pragma unroll
                for (int c = 0; c < 4; c++) {
                    MBAR_EXPECT_TX(MBH + c * 8, 16384);
                    bulk_g2s(HSb + (unsigned)c * 16384u, hsrc + c * 16384, 16384, MBH + c * 8);
                }
            } else if (tid >= 128) {
                // overlap barrier latency with output writes
                int u = tid - 128;
                int r = u >> 1, part = u & 1;
                float* od = out + (size_t)r * TT * HH + (size_t)s * HH + cta * 8 + part * 4;
                *reinterpret_cast<uint4*>(od) =
                    *reinterpret_cast<const uint4*>(&S.outs[r * 8 + part * 4]);
            }
            // no post-barrier sync: next iteration's mbar_wait gates everything
        } else {
            if (tid >= 128) {
                int u = tid - 128;
                int r = u >> 1, part = u & 1;
                float* od = out + (size_t)r * TT * HH + (size_t)s * HH + cta * 8 + part * 4;
                *reinterpret_cast<uint4*>(od) =
                    *reinterpret_cast<const uint4*>(&S.outs[r * 8 + part * 4]);
            }
        }
    }
}

// ---------------- launch ----------------
extern "C" void kernel_launch(void* const* d_in, const int* in_sizes, int n_in,
                              void* d_out, int out_size) {
    const float* x    = (const float*)d_in[0];
    const float* Wsw  = (const float*)d_in[1];
    const float* bsw  = (const float*)d_in[2];
    const float* Wsm  = (const float*)d_in[3];
    const float* bsm  = (const float*)d_in[4];
    const float* Wss  = (const float*)d_in[5];
    const float* bss  = (const float*)d_in[6];
    const float* Wiw  = (const float*)d_in[7];
    const float* biw  = (const float*)d_in[8];
    const float* Wim  = (const float*)d_in[9];
    const float* bim  = (const float*)d_in[10];
    const float* Wis  = (const float*)d_in[11];
    const float* bis  = (const float*)d_in[12];
    const float* Wtcx = (const float*)d_in[13];
    const float* Wtch = (const float*)d_in[14];
    const float* btc  = (const float*)d_in[15];
    float* out = (float*)d_out;

    cudaFuncSetAttribute(phase1_kernel, cudaFuncAttributeMaxDynamicSharedMemorySize,
                         (int)sizeof(P1Smem));
    cudaFuncSetAttribute(phase2_kernel, cudaFuncAttributeMaxDynamicSharedMemorySize,
                         (int)sizeof(P2Smem));

    dim3 g1(512, 16);
    phase1_kernel<<<g1, 256, sizeof(P1Smem)>>>(x, Wsw, Wsm, Wss, Wtcx, bsw, bsm, bss, btc);

    phase2_kernel<<<NCTA2, THR2, sizeof(P2Smem)>>>(out, Wtch, Wiw, Wim, Wis, biw, bim, bis);
}